// round 14
// baseline (speedup 1.0000x reference)
#include <cuda_runtime.h>
#include <math.h>

#define B 64
#define S 512
#define H 1024
#define L 5
#define EMS 8   // emission row stride (padded for aligned float4 loads)

#define LOG2E_F 1.4426950408889634f
#define LN2_F   0.6931471805599453f

// Scratch (static device globals — allocation-free per harness rules)
__device__ float g_emis[B * S * EMS];
__device__ float g_num[B];
__device__ float g_logz[B];

__device__ __forceinline__ float ex2f_(float x) {
    float r; asm("ex2.approx.ftz.f32 %0, %1;" : "=f"(r) : "f"(x)); return r;
}
__device__ __forceinline__ float lg2f_(float x) {
    float r; asm("lg2.approx.f32 %0, %1;" : "=f"(r) : "f"(x)); return r;
}

__device__ __forceinline__ void dot4(float& a, const float4& v, const float4& wv) {
    a = fmaf(v.x, wv.x, fmaf(v.y, wv.y, fmaf(v.z, wv.z, fmaf(v.w, wv.w, a))));
}

// ---------------------------------------------------------------------------
// Kernel 1: emissions = relu(feats @ W + b)  (UNCHANGED except stride-8 out)
// ---------------------------------------------------------------------------
__global__ __launch_bounds__(256, 3) void k_emis(const float* __restrict__ feats,
                                                 const float* __restrict__ Wg,
                                                 const float* __restrict__ bias) {
    __shared__ float sWT[5 * 1024];   // sWT[l*1024 + k] = W[k][l]
    const int t = threadIdx.x;
    for (int i = t; i < H * L; i += 256) {
        const int k = i / 5, l = i - 5 * k;
        sWT[l * 1024 + k] = Wg[i];
    }
    __syncthreads();

    const int lane = t & 31, w = t >> 5;
    const int row0 = blockIdx.x * 32 + w * 4;
    const float4* p0 = (const float4*)(feats + (size_t)(row0 + 0) * H);
    const float4* p1 = (const float4*)(feats + (size_t)(row0 + 1) * H);
    const float4* p2 = (const float4*)(feats + (size_t)(row0 + 2) * H);
    const float4* p3 = (const float4*)(feats + (size_t)(row0 + 3) * H);

    float acc[4][5];
#pragma unroll
    for (int r = 0; r < 4; r++)
#pragma unroll
        for (int l = 0; l < 5; l++) acc[r][l] = 0.f;

    float4 xa0 = p0[lane],      xa1 = p1[lane],      xa2 = p2[lane],      xa3 = p3[lane];
    float4 xb0 = p0[lane + 32], xb1 = p1[lane + 32], xb2 = p2[lane + 32], xb3 = p3[lane + 32];

#pragma unroll
    for (int i = 0; i < 8; i++) {
        float4 xc0, xc1, xc2, xc3;
        if (i < 6) {
            const int idx = lane + 32 * (i + 2);
            xc0 = p0[idx]; xc1 = p1[idx]; xc2 = p2[idx]; xc3 = p3[idx];
        }
        const int ko = (lane + 32 * i) * 4;
        const float4 w0 = *(const float4*)(sWT + 0 * 1024 + ko);
        const float4 w1 = *(const float4*)(sWT + 1 * 1024 + ko);
        const float4 w2 = *(const float4*)(sWT + 2 * 1024 + ko);
        const float4 w3 = *(const float4*)(sWT + 3 * 1024 + ko);
        const float4 w4 = *(const float4*)(sWT + 4 * 1024 + ko);

        dot4(acc[0][0], xa0, w0); dot4(acc[0][1], xa0, w1);
        dot4(acc[0][2], xa0, w2); dot4(acc[0][3], xa0, w3);
        dot4(acc[0][4], xa0, w4);
        dot4(acc[1][0], xa1, w0); dot4(acc[1][1], xa1, w1);
        dot4(acc[1][2], xa1, w2); dot4(acc[1][3], xa1, w3);
        dot4(acc[1][4], xa1, w4);
        dot4(acc[2][0], xa2, w0); dot4(acc[2][1], xa2, w1);
        dot4(acc[2][2], xa2, w2); dot4(acc[2][3], xa2, w3);
        dot4(acc[2][4], xa2, w4);
        dot4(acc[3][0], xa3, w0); dot4(acc[3][1], xa3, w1);
        dot4(acc[3][2], xa3, w2); dot4(acc[3][3], xa3, w3);
        dot4(acc[3][4], xa3, w4);

        xa0 = xb0; xa1 = xb1; xa2 = xb2; xa3 = xb3;
        if (i < 6) { xb0 = xc0; xb1 = xc1; xb2 = xc2; xb3 = xc3; }
    }

#pragma unroll
    for (int r = 0; r < 4; r++)
#pragma unroll
        for (int l = 0; l < 5; l++) {
#pragma unroll
            for (int d = 16; d > 0; d >>= 1)
                acc[r][l] += __shfl_xor_sync(0xffffffffu, acc[r][l], d);
        }

    float val = 0.f;
#pragma unroll
    for (int r = 0; r < 4; r++)
#pragma unroll
        for (int l = 0; l < 5; l++)
            if (lane == r * 5 + l) val = acc[r][l];
    if (lane < 20) {
        const int r = lane / 5, l = lane - 5 * (lane / 5);
        g_emis[(size_t)(row0 + r) * EMS + l] = fmaxf(val + bias[l], 0.f);
    }
}

// packed [5]->[5] map composition: returns f∘g (g applied first)
__device__ __forceinline__ int fcompose(int f, int g) {
    int r = 0;
#pragma unroll
    for (int x = 0; x < 5; x++) {
        int gx = (g >> (3 * x)) & 7;
        int fx = (f >> (3 * gx)) & 7;
        r |= fx << (3 * x);
    }
    return r;
}

// One exact Viterbi step on replicated state (all lanes hold v0..v4).
// Bit-identical op order to reference: c_i = v_i + T[i][j]; best = fmax-tree;
// v_j = best + e_j.  Returns new values through nv[].
__device__ __forceinline__ void vstep(const float T[5][5],
                                      const float v[5], const float e[5],
                                      float nv[5]) {
#pragma unroll
    for (int j = 0; j < 5; j++) {
        float c0 = v[0] + T[0][j];
        float c1 = v[1] + T[1][j];
        float c2 = v[2] + T[2][j];
        float c3 = v[3] + T[3][j];
        float c4 = v[4] + T[4][j];
        float best = fmaxf(fmaxf(fmaxf(c0, c1), fmaxf(c2, c3)), c4);
        nv[j] = best + e[j];
    }
}

// Same step but also extracts first-occurrence argmax backpointers packed
// 3 bits x 5 into *pk.
__device__ __forceinline__ void vstep_bp(const float T[5][5],
                                         const float v[5], const float e[5],
                                         float nv[5], int* pk) {
    int packed = 0;
#pragma unroll
    for (int j = 0; j < 5; j++) {
        float c0 = v[0] + T[0][j];
        float c1 = v[1] + T[1][j];
        float c2 = v[2] + T[2][j];
        float c3 = v[3] + T[3][j];
        float c4 = v[4] + T[4][j];
        float best = fmaxf(fmaxf(fmaxf(c0, c1), fmaxf(c2, c3)), c4);
        int bp = (c0 == best) ? 0 : (c1 == best) ? 1
               : (c2 == best) ? 2 : (c3 == best) ? 3 : 4;
        nv[j] = best + e[j];
        packed |= bp << (3 * j);
    }
    *pk = packed;
}

// ---------------------------------------------------------------------------
// Kernel 2: CRF. Grid = 128 blocks x 288 threads:
//   blocks 0..63  : warp 8 = pass-A Viterbi (replicated, no shfl) storing
//       exact 64-step boundaries; warps 0..7 sleep then run pass-B chunks
//       (replicated, with backpointers); warp 8 compose-scan backtrace.
//   blocks 64..127: warps 0..7 forward chunk matrices (lane-0-exponent
//       renorm) -> warp 0 combine (logZ); warp 8 numerator.
// ---------------------------------------------------------------------------
__global__ __launch_bounds__(288) void k_crf(const int* __restrict__ labels,
                                             const float* __restrict__ start_tr,
                                             const float* __restrict__ end_tr,
                                             const float* __restrict__ trans,
                                             const float* __restrict__ wts,
                                             float* __restrict__ out) {
    const int bid = blockIdx.x;
    const int tid = threadIdx.x;
    const int wid = tid >> 5;
    const int lane = tid & 31;

    if (bid < 64) {
        // ==================== Viterbi block (batch = bid) ==================
        const int b = bid;
        const float* em = g_emis + (size_t)b * (S * EMS);
        __shared__ int   s_bp[S];
        __shared__ float sBnd[8 * 5];

        if (wid == 8) {
            // ============ pass A: replicated value-only Viterbi ============
            float T[5][5];
#pragma unroll
            for (int i = 0; i < 5; i++)
#pragma unroll
                for (int j = 0; j < 5; j++) T[i][j] = trans[i * 5 + j];

            float v[5];
#pragma unroll
            for (int j = 0; j < 5; j++) v[j] = start_tr[j] + em[j];
            if (lane == 0) {
#pragma unroll
                for (int j = 0; j < 5; j++) sBnd[j] = v[j];
            }

            float eb[8][5];
#pragma unroll
            for (int u = 0; u < 8; u++) {
                const float4 q = *(const float4*)(em + (1 + u) * EMS);
                eb[u][0] = q.x; eb[u][1] = q.y; eb[u][2] = q.z; eb[u][3] = q.w;
                eb[u][4] = em[(1 + u) * EMS + 4];
            }

            for (int tb = 1; tb < S; tb += 8) {
                float en[8][5];
#pragma unroll
                for (int u = 0; u < 8; u++) {
                    const int tt = tb + 8 + u;
                    if (tt < S) {
                        const float4 q = *(const float4*)(em + tt * EMS);
                        en[u][0] = q.x; en[u][1] = q.y; en[u][2] = q.z;
                        en[u][3] = q.w; en[u][4] = em[tt * EMS + 4];
                    } else {
                        en[u][0] = en[u][1] = en[u][2] = en[u][3] = en[u][4] = 0.f;
                    }
                }
#pragma unroll
                for (int u = 0; u < 8; u++) {
                    const int tcur = tb + u;
                    if (tcur < S) {
                        float nv[5];
                        vstep(T, v, eb[u], nv);
#pragma unroll
                        for (int j = 0; j < 5; j++) v[j] = nv[j];
                        if (((tcur & 63) == 0) && lane == 0) {
#pragma unroll
                            for (int j = 0; j < 5; j++)
                                sBnd[(tcur >> 6) * 5 + j] = v[j];
                        }
                    }
                }
#pragma unroll
                for (int u = 0; u < 8; u++)
#pragma unroll
                    for (int j = 0; j < 5; j++) eb[u][j] = en[u][j];
            }

            // final tag: first-occurrence argmax over (v + end)
            float sc[5];
#pragma unroll
            for (int j = 0; j < 5; j++) sc[j] = v[j] + end_tr[j];
            float bb = fmaxf(fmaxf(fmaxf(sc[0], sc[1]), fmaxf(sc[2], sc[3])), sc[4]);
            int last = (sc[0] == bb) ? 0 : (sc[1] == bb) ? 1
                     : (sc[2] == bb) ? 2 : (sc[3] == bb) ? 3 : 4;

            __syncthreads();   // boundaries ready -> wake warps 0..7
            __syncthreads();   // s_bp complete

            // ---- backtrace via suffix scan of packed [5]->[5] maps --------
            const int IDMAP = 0 | (1 << 3) | (2 << 6) | (3 << 9) | (4 << 12);
            int wv[16];
            const int tb2 = lane * 16;
#pragma unroll
            for (int u = 0; u < 16; u++) wv[u] = s_bp[tb2 + u];
            if (lane == 0) wv[0] = IDMAP;

            int G = wv[0];
#pragma unroll
            for (int u = 1; u < 16; u++) G = fcompose(G, wv[u]);

            int Tm = G;
#pragma unroll
            for (int d = 1; d < 32; d <<= 1) {
                int o = __shfl_down_sync(0xffffffffu, Tm, d);
                Tm = (lane + d < 32) ? fcompose(Tm, o) : Tm;
            }
            int E = __shfl_down_sync(0xffffffffu, Tm, 1);
            if (lane == 31) E = IDMAP;

            int tag = (E >> (3 * last)) & 7;
            float* po = out + 1 + (size_t)b * S;
            po[tb2 + 15] = (float)tag;
#pragma unroll
            for (int u = 15; u >= 1; u--) {
                tag = (wv[u] >> (3 * tag)) & 7;
                po[tb2 + u - 1] = (float)tag;
            }
        } else {
            __syncthreads();   // sleep until pass-A boundaries ready

            // ---- pass B: replicated Viterbi chunk with backpointers -------
            float T[5][5];
#pragma unroll
            for (int i = 0; i < 5; i++)
#pragma unroll
                for (int j = 0; j < 5; j++) T[i][j] = trans[i * 5 + j];

            float v[5];
#pragma unroll
            for (int j = 0; j < 5; j++) v[j] = sBnd[wid * 5 + j];
            const int t0 = 1 + 64 * wid;
            const int t1 = (t0 + 64 < S) ? (t0 + 64) : S;

            float eb[8][5];
#pragma unroll
            for (int u = 0; u < 8; u++) {
                const int tt = t0 + u;
                if (tt < t1) {
                    const float4 q = *(const float4*)(em + tt * EMS);
                    eb[u][0] = q.x; eb[u][1] = q.y; eb[u][2] = q.z;
                    eb[u][3] = q.w; eb[u][4] = em[tt * EMS + 4];
                } else {
                    eb[u][0] = eb[u][1] = eb[u][2] = eb[u][3] = eb[u][4] = 0.f;
                }
            }

            for (int tb = t0; tb < t1; tb += 8) {
                float en[8][5];
#pragma unroll
                for (int u = 0; u < 8; u++) {
                    const int tt = tb + 8 + u;
                    if (tt < t1) {
                        const float4 q = *(const float4*)(em + tt * EMS);
                        en[u][0] = q.x; en[u][1] = q.y; en[u][2] = q.z;
                        en[u][3] = q.w; en[u][4] = em[tt * EMS + 4];
                    } else {
                        en[u][0] = en[u][1] = en[u][2] = en[u][3] = en[u][4] = 0.f;
                    }
                }
#pragma unroll
                for (int u = 0; u < 8; u++) {
                    const int tcur = tb + u;
                    if (tcur < t1) {
                        float nv[5]; int pk;
                        vstep_bp(T, v, eb[u], nv, &pk);
#pragma unroll
                        for (int j = 0; j < 5; j++) v[j] = nv[j];
                        if (lane == 0) s_bp[tcur] = pk;
                    }
                }
#pragma unroll
                for (int u = 0; u < 8; u++)
#pragma unroll
                    for (int j = 0; j < 5; j++) eb[u][j] = en[u][j];
            }
            __syncthreads();   // s_bp complete
        }
        return;
    }

    // ===================== forward + numerator block =======================
    const int b = bid - 64;
    const float* em = g_emis + (size_t)b * (S * EMS);
    __shared__ float sM[8 * 25];
    __shared__ int   sC[8];

    if (wid == 8) {
        // ========================== numerator ==============================
        const int* lb = labels + b * S;
        float acc = 0.f;
#pragma unroll
        for (int it = 0; it < S / 32; it++) {
            const int s2 = lane + it * 32;
            int l0 = lb[s2];
            float term = wts[l0] * em[s2 * EMS + l0];
            if (s2 + 1 < S) {
                int l1 = lb[s2 + 1];
                term += trans[l0 * 5 + l1];
            }
            acc += term;
        }
#pragma unroll
        for (int d = 16; d > 0; d >>= 1)
            acc += __shfl_xor_sync(0xffffffffu, acc, d);
        if (lane == 0)
            g_num[b] = acc + start_tr[lb[0]] + end_tr[lb[S - 1]];
        return;
    }

    {
        // ---- forward: chunk transfer matrix (scaled prob) -----------------
        const int cj = lane % 5;        // column j
        const int ci = lane / 5;        // row i (>=5 for lanes 25..31)
        const bool act = lane < 25;
        const int b5 = lane - cj;       // 5*i
        const float E0 = ex2f_(trans[0 * 5 + cj] * LOG2E_F);
        const float E1 = ex2f_(trans[1 * 5 + cj] * LOG2E_F);
        const float E2 = ex2f_(trans[2 * 5 + cj] * LOG2E_F);
        const float E3 = ex2f_(trans[3 * 5 + cj] * LOG2E_F);
        const float E4 = ex2f_(trans[4 * 5 + cj] * LOG2E_F);

        float m = (act && ci == cj) ? 1.f : 0.f;
        int cexp = 0;
        const int t0 = 1 + 64 * wid;
        const int t1 = (t0 + 64 < S) ? (t0 + 64) : S;

        float fb[8];
#pragma unroll
        for (int u = 0; u < 8; u++) {
            int tt = t0 + u;
            fb[u] = (tt < t1) ? ex2f_(em[tt * EMS + cj] * LOG2E_F) : 1.f;
        }

        for (int tb = t0; tb < t1; tb += 8) {
            float fn[8];
#pragma unroll
            for (int u = 0; u < 8; u++) {
                int tt = tb + 8 + u;
                fn[u] = (tt < t1) ? ex2f_(em[tt * EMS + cj] * LOG2E_F) : 1.f;
            }
#pragma unroll
            for (int u = 0; u < 8; u++) {
                if (tb + u < t1) {
                    float a0 = __shfl_sync(0xffffffffu, m, b5 + 0);
                    float a1 = __shfl_sync(0xffffffffu, m, b5 + 1);
                    float a2 = __shfl_sync(0xffffffffu, m, b5 + 2);
                    float a3 = __shfl_sync(0xffffffffu, m, b5 + 3);
                    float a4 = __shfl_sync(0xffffffffu, m, b5 + 4);
                    float sm = (fmaf(a0, E0, a1 * E1) + fmaf(a2, E2, a3 * E3))
                               + a4 * E4;
                    m = act ? sm * fb[u] : 0.f;
                }
            }
            // renormalize by 2^-k, k = exponent of lane 0's entry (M_00):
            // states stay within ~2^7 of each other and grow (f >= 1), so
            // lane-0 scaling keeps everything in range. Exact power-of-2.
            float m0 = __shfl_sync(0xffffffffu, m, 0);
            int kx = ((__float_as_int(m0) >> 23) & 255) - 127;
            m *= __int_as_float((127 - kx) << 23);
            cexp += kx;
#pragma unroll
            for (int u = 0; u < 8; u++) fb[u] = fn[u];
        }
        if (act) sM[wid * 25 + lane] = m;
        if (lane == 0) sC[wid] = cexp;
        asm volatile("bar.sync 1, 256;" ::: "memory");

        if (wid == 0) {
            const bool aj = lane < 5;
            float v = aj ? ex2f_((start_tr[lane] + em[lane]) * LOG2E_F) : 0.f;
            int ct = 0;
#pragma unroll
            for (int c = 0; c < 8; c++) {
                float a0 = __shfl_sync(0xffffffffu, v, 0);
                float a1 = __shfl_sync(0xffffffffu, v, 1);
                float a2 = __shfl_sync(0xffffffffu, v, 2);
                float a3 = __shfl_sync(0xffffffffu, v, 3);
                float a4 = __shfl_sync(0xffffffffu, v, 4);
                float nv = 0.f;
                if (aj) {
                    const float* Mc = sM + c * 25 + lane;
                    nv = fmaf(a0, Mc[0], fmaf(a1, Mc[5], fmaf(a2, Mc[10],
                         fmaf(a3, Mc[15], a4 * Mc[20]))));
                }
                float n0 = __shfl_sync(0xffffffffu, nv, 0);
                int kx = ((__float_as_int(n0) >> 23) & 255) - 127;
                v = nv * __int_as_float((127 - kx) << 23);
                ct += sC[c] + kx;
            }
            float r = aj ? v * ex2f_(end_tr[lane] * LOG2E_F) : 0.f;
            r += __shfl_xor_sync(0xffffffffu, r, 1);
            r += __shfl_xor_sync(0xffffffffu, r, 2);
            r += __shfl_xor_sync(0xffffffffu, r, 4);
            if (lane == 0)
                g_logz[b] = ((float)ct + lg2f_(fmaxf(r, 1e-38f))) * LN2_F;
        }
    }
}

// ---------------------------------------------------------------------------
// Kernel 3: loss = -sum_b(num_b - logz_b) / (B*S)
// ---------------------------------------------------------------------------
__global__ __launch_bounds__(64) void k_final(float* __restrict__ out) {
    const int t = threadIdx.x;
    float v = g_num[t] - g_logz[t];
#pragma unroll
    for (int d = 16; d > 0; d >>= 1)
        v += __shfl_xor_sync(0xffffffffu, v, d);
    __shared__ float sh[2];
    if ((t & 31) == 0) sh[t >> 5] = v;
    __syncthreads();
    if (t == 0) out[0] = -(sh[0] + sh[1]) * (1.0f / (float)(B * S));
}

// ---------------------------------------------------------------------------
// Launch. Inputs: feats f32, labels i32, mask bool (all ones, unused),
// W_tag f32, b_tag f32, start_trans f32, end_trans f32, trans f32, weights f32.
// Output: [loss, paths(B*S)] as float32.
// ---------------------------------------------------------------------------
extern "C" void kernel_launch(void* const* d_in, const int* in_sizes, int n_in,
                              void* d_out, int out_size) {
    (void)in_sizes; (void)n_in; (void)out_size;
    const float* feats  = (const float*)d_in[0];
    const int*   labels = (const int*)d_in[1];
    const float* W      = (const float*)d_in[3];
    const float* bias   = (const float*)d_in[4];
    const float* st     = (const float*)d_in[5];
    const float* en     = (const float*)d_in[6];
    const float* tr     = (const float*)d_in[7];
    const float* wt     = (const float*)d_in[8];
    float* out = (float*)d_out;

    k_emis<<<1024, 256>>>(feats, W, bias);
    k_crf<<<128, 288>>>(labels, st, en, tr, wt, out);
    k_final<<<1, 64>>>(out);
}

// round 15
// speedup vs baseline: 1.1729x; 1.1729x over previous
#include <cuda_runtime.h>
#include <math.h>

#define B 64
#define S 512
#define H 1024
#define L 5
#define EMS 8   // emission row stride (padded for aligned float4 loads)

#define LOG2E_F 1.4426950408889634f
#define LN2_F   0.6931471805599453f

// Scratch (static device globals). +16 pad: branch-free prefetch reads t=512.
__device__ float g_emis[B * S * EMS + 16];
__device__ float g_num[B];
__device__ float g_logz[B];

__device__ __forceinline__ float ex2f_(float x) {
    float r; asm("ex2.approx.ftz.f32 %0, %1;" : "=f"(r) : "f"(x)); return r;
}
__device__ __forceinline__ float lg2f_(float x) {
    float r; asm("lg2.approx.f32 %0, %1;" : "=f"(r) : "f"(x)); return r;
}

__device__ __forceinline__ void dot4(float& a, const float4& v, const float4& wv) {
    a = fmaf(v.x, wv.x, fmaf(v.y, wv.y, fmaf(v.z, wv.z, fmaf(v.w, wv.w, a))));
}

// ---------------------------------------------------------------------------
// Kernel 1: emissions = relu(feats @ W + b)
// 2 rows/warp (regs ~55 -> 4 blocks/SM, 32 warps). Lane owns float4 slice
// (lane + 32*i): contiguous 512B warp LDGs, prefetch distance 2.
// W transposed in smem (LDS.128, conflict-free). 2048 blocks x 256.
// ---------------------------------------------------------------------------
__global__ __launch_bounds__(256, 4) void k_emis(const float* __restrict__ feats,
                                                 const float* __restrict__ Wg,
                                                 const float* __restrict__ bias) {
    __shared__ float sWT[5 * 1024];   // sWT[l*1024 + k] = W[k][l]
    const int t = threadIdx.x;
    for (int i = t; i < H * L; i += 256) {
        const int k = i / 5, l = i - 5 * k;
        sWT[l * 1024 + k] = Wg[i];
    }
    __syncthreads();

    const int lane = t & 31, w = t >> 5;
    const int row0 = blockIdx.x * 16 + w * 2;
    const float4* p0 = (const float4*)(feats + (size_t)(row0 + 0) * H);
    const float4* p1 = (const float4*)(feats + (size_t)(row0 + 1) * H);

    float acc[2][5];
#pragma unroll
    for (int r = 0; r < 2; r++)
#pragma unroll
        for (int l = 0; l < 5; l++) acc[r][l] = 0.f;

    float4 xa0 = p0[lane],      xa1 = p1[lane];
    float4 xb0 = p0[lane + 32], xb1 = p1[lane + 32];

#pragma unroll
    for (int i = 0; i < 8; i++) {
        float4 xc0, xc1;
        if (i < 6) {
            const int idx = lane + 32 * (i + 2);
            xc0 = p0[idx]; xc1 = p1[idx];
        }
        const int ko = (lane + 32 * i) * 4;
        const float4 w0 = *(const float4*)(sWT + 0 * 1024 + ko);
        const float4 w1 = *(const float4*)(sWT + 1 * 1024 + ko);
        const float4 w2 = *(const float4*)(sWT + 2 * 1024 + ko);
        const float4 w3 = *(const float4*)(sWT + 3 * 1024 + ko);
        const float4 w4 = *(const float4*)(sWT + 4 * 1024 + ko);

        dot4(acc[0][0], xa0, w0); dot4(acc[0][1], xa0, w1);
        dot4(acc[0][2], xa0, w2); dot4(acc[0][3], xa0, w3);
        dot4(acc[0][4], xa0, w4);
        dot4(acc[1][0], xa1, w0); dot4(acc[1][1], xa1, w1);
        dot4(acc[1][2], xa1, w2); dot4(acc[1][3], xa1, w3);
        dot4(acc[1][4], xa1, w4);

        xa0 = xb0; xa1 = xb1;
        if (i < 6) { xb0 = xc0; xb1 = xc1; }
    }

    // butterfly reduce the 10 accumulators over the 32 lanes
#pragma unroll
    for (int r = 0; r < 2; r++)
#pragma unroll
        for (int l = 0; l < 5; l++) {
#pragma unroll
            for (int d = 16; d > 0; d >>= 1)
                acc[r][l] += __shfl_xor_sync(0xffffffffu, acc[r][l], d);
        }

    float val = 0.f;
#pragma unroll
    for (int r = 0; r < 2; r++)
#pragma unroll
        for (int l = 0; l < 5; l++)
            if (lane == r * 5 + l) val = acc[r][l];
    if (lane < 10) {
        const int r = lane / 5, l = lane - 5 * (lane / 5);
        g_emis[(size_t)(row0 + r) * EMS + l] = fmaxf(val + bias[l], 0.f);
    }
}

// packed [5]->[5] map composition: returns f∘g (g applied first)
__device__ __forceinline__ int fcompose(int f, int g) {
    int r = 0;
#pragma unroll
    for (int x = 0; x < 5; x++) {
        int gx = (g >> (3 * x)) & 7;
        int fx = (f >> (3 * gx)) & 7;
        r |= fx << (3 * x);
    }
    return r;
}

// ---------------------------------------------------------------------------
// Kernel 2: CRF. Grid = 128 blocks x 288 threads:
//   blocks 0..63  : warp 8 = pass-A Viterbi (shfl-step, BRANCH-FREE groups,
//       bit-exact), boundary store per 64-step super-group; warps 0..7 sleep
//       then pass-B backpointer chunks (branch-free); warp 8 backtrace.
//   blocks 64..127: warps 0..7 forward chunk matrices -> warp 0 combine
//       (logZ); warp 8 numerator.
// ---------------------------------------------------------------------------
__global__ __launch_bounds__(288) void k_crf(const int* __restrict__ labels,
                                             const float* __restrict__ start_tr,
                                             const float* __restrict__ end_tr,
                                             const float* __restrict__ trans,
                                             const float* __restrict__ wts,
                                             float* __restrict__ out) {
    const int bid = blockIdx.x;
    const int tid = threadIdx.x;
    const int wid = tid >> 5;
    const int lane = tid & 31;

    if (bid < 64) {
        // ==================== Viterbi block (batch = bid) ==================
        const int b = bid;
        const float* em = g_emis + (size_t)b * (S * EMS);
        __shared__ int   s_bp[S];
        __shared__ float sBnd[8 * 5];

        if (wid == 8) {
            // ===== pass A: shfl-step value-only Viterbi (branch-free) ======
            const int j = lane % 5;   // lanes 0..4 canonical, others mirror
            const float T0 = trans[0 * 5 + j];
            const float T1 = trans[1 * 5 + j];
            const float T2 = trans[2 * 5 + j];
            const float T3 = trans[3 * 5 + j];
            const float T4 = trans[4 * 5 + j];
            float v = start_tr[j] + em[j];
            if (lane < 5) sBnd[lane] = v;

            float ec[8], en[8];
#pragma unroll
            for (int u = 0; u < 8; u++) ec[u] = em[(1 + u) * EMS + j];

            int tt = 1;   // index of ec[0]
#define VSTEP(EV) { \
                float v0 = __shfl_sync(0xffffffffu, v, 0); \
                float v1 = __shfl_sync(0xffffffffu, v, 1); \
                float v2 = __shfl_sync(0xffffffffu, v, 2); \
                float v3 = __shfl_sync(0xffffffffu, v, 3); \
                float v4 = __shfl_sync(0xffffffffu, v, 4); \
                float c0 = v0 + T0, c1 = v1 + T1, c2 = v2 + T2; \
                float c3 = v3 + T3, c4 = v4 + T4; \
                float best = fmaxf(fmaxf(fmaxf(c0, c1), fmaxf(c2, c3)), c4); \
                v = best + (EV); }

#pragma unroll 1
            for (int sg = 0; sg < 7; sg++) {        // 7 x 64 steps (t 1..448)
#pragma unroll
                for (int grp = 0; grp < 8; grp++) {
#pragma unroll
                    for (int u = 0; u < 8; u++) en[u] = em[(tt + 8 + u) * EMS + j];
#pragma unroll
                    for (int u = 0; u < 8; u++) VSTEP(ec[u])
                    tt += 8;
#pragma unroll
                    for (int u = 0; u < 8; u++) ec[u] = en[u];
                }
                if (lane < 5) sBnd[(sg + 1) * 5 + lane] = v;
            }
            // epilogue: 56 steps (t 449..504) + 7 tail (505..511)
#pragma unroll 1
            for (int grp = 0; grp < 7; grp++) {
#pragma unroll
                for (int u = 0; u < 8; u++) en[u] = em[(tt + 8 + u) * EMS + j];
#pragma unroll
                for (int u = 0; u < 8; u++) VSTEP(ec[u])
                tt += 8;
#pragma unroll
                for (int u = 0; u < 8; u++) ec[u] = en[u];
            }
#pragma unroll
            for (int u = 0; u < 7; u++) VSTEP(ec[u])
#undef VSTEP

            // final tag: first-occurrence argmax over (v + end)
            float sc = v + end_tr[j];
            float s0 = __shfl_sync(0xffffffffu, sc, 0);
            float s1 = __shfl_sync(0xffffffffu, sc, 1);
            float s2 = __shfl_sync(0xffffffffu, sc, 2);
            float s3 = __shfl_sync(0xffffffffu, sc, 3);
            float s4 = __shfl_sync(0xffffffffu, sc, 4);
            float bb = fmaxf(fmaxf(fmaxf(s0, s1), fmaxf(s2, s3)), s4);
            int last = (s0 == bb) ? 0 : (s1 == bb) ? 1
                     : (s2 == bb) ? 2 : (s3 == bb) ? 3 : 4;

            __syncthreads();   // boundaries ready -> wake warps 0..7
            __syncthreads();   // s_bp complete

            // ---- backtrace via suffix scan of packed [5]->[5] maps --------
            const int IDMAP = 0 | (1 << 3) | (2 << 6) | (3 << 9) | (4 << 12);
            int wv[16];
            const int tb2 = lane * 16;
#pragma unroll
            for (int u = 0; u < 16; u++) wv[u] = s_bp[tb2 + u];
            if (lane == 0) wv[0] = IDMAP;

            int G = wv[0];
#pragma unroll
            for (int u = 1; u < 16; u++) G = fcompose(G, wv[u]);

            int Tm = G;
#pragma unroll
            for (int d = 1; d < 32; d <<= 1) {
                int o = __shfl_down_sync(0xffffffffu, Tm, d);
                Tm = (lane + d < 32) ? fcompose(Tm, o) : Tm;
            }
            int E = __shfl_down_sync(0xffffffffu, Tm, 1);
            if (lane == 31) E = IDMAP;

            int tag = (E >> (3 * last)) & 7;
            float* po = out + 1 + (size_t)b * S;
            po[tb2 + 15] = (float)tag;
#pragma unroll
            for (int u = 15; u >= 1; u--) {
                tag = (wv[u] >> (3 * tag)) & 7;
                po[tb2 + u - 1] = (float)tag;
            }
        } else {
            __syncthreads();   // sleep until pass-A boundaries ready

            // ---- pass B: shfl-step Viterbi chunk with backpointers --------
            const int j = lane % 5;
            const float T0 = trans[0 * 5 + j];
            const float T1 = trans[1 * 5 + j];
            const float T2 = trans[2 * 5 + j];
            const float T3 = trans[3 * 5 + j];
            const float T4 = trans[4 * 5 + j];
            float v = sBnd[wid * 5 + j];
            int tt = 1 + 64 * wid;
            const int nfull = (wid < 7) ? 8 : 7;   // groups of 8 steps

            float ec[8], en[8];
#pragma unroll
            for (int u = 0; u < 8; u++) ec[u] = em[(tt + u) * EMS + j];

#define VSTEPB(EV, TC) { \
                float v0 = __shfl_sync(0xffffffffu, v, 0); \
                float v1 = __shfl_sync(0xffffffffu, v, 1); \
                float v2 = __shfl_sync(0xffffffffu, v, 2); \
                float v3 = __shfl_sync(0xffffffffu, v, 3); \
                float v4 = __shfl_sync(0xffffffffu, v, 4); \
                float c0 = v0 + T0, c1 = v1 + T1, c2 = v2 + T2; \
                float c3 = v3 + T3, c4 = v4 + T4; \
                float best = fmaxf(fmaxf(fmaxf(c0, c1), fmaxf(c2, c3)), c4); \
                int bp = (c0 == best) ? 0 : (c1 == best) ? 1 \
                       : (c2 == best) ? 2 : (c3 == best) ? 3 : 4; \
                v = best + (EV); \
                unsigned pk = __reduce_add_sync(0xffffffffu, \
                              (lane < 5) ? ((unsigned)bp << (3 * j)) : 0u); \
                if (lane == 0) s_bp[(TC)] = (int)pk; }

#pragma unroll 1
            for (int grp = 0; grp < nfull; grp++) {
#pragma unroll
                for (int u = 0; u < 8; u++) en[u] = em[(tt + 8 + u) * EMS + j];
#pragma unroll
                for (int u = 0; u < 8; u++) VSTEPB(ec[u], tt + u)
                tt += 8;
#pragma unroll
                for (int u = 0; u < 8; u++) ec[u] = en[u];
            }
            if (wid == 7) {
#pragma unroll
                for (int u = 0; u < 7; u++) VSTEPB(ec[u], tt + u)
            }
#undef VSTEPB
            __syncthreads();   // s_bp complete
        }
        return;
    }

    // ===================== forward + numerator block =======================
    const int b = bid - 64;
    const float* em = g_emis + (size_t)b * (S * EMS);
    __shared__ float sM[8 * 25];
    __shared__ int   sC[8];

    if (wid == 8) {
        // ========================== numerator ==============================
        const int* lb = labels + b * S;
        float acc = 0.f;
#pragma unroll
        for (int it = 0; it < S / 32; it++) {
            const int s2 = lane + it * 32;
            int l0 = lb[s2];
            float term = wts[l0] * em[s2 * EMS + l0];
            if (s2 + 1 < S) {
                int l1 = lb[s2 + 1];
                term += trans[l0 * 5 + l1];
            }
            acc += term;
        }
#pragma unroll
        for (int d = 16; d > 0; d >>= 1)
            acc += __shfl_xor_sync(0xffffffffu, acc, d);
        if (lane == 0)
            g_num[b] = acc + start_tr[lb[0]] + end_tr[lb[S - 1]];
        return;
    }

    {
        // ---- forward: chunk transfer matrix (scaled prob) -----------------
        const int cj = lane % 5;        // column j
        const int ci = lane / 5;        // row i (>=5 for lanes 25..31)
        const bool act = lane < 25;
        const int b5 = lane - cj;       // 5*i
        const float E0 = ex2f_(trans[0 * 5 + cj] * LOG2E_F);
        const float E1 = ex2f_(trans[1 * 5 + cj] * LOG2E_F);
        const float E2 = ex2f_(trans[2 * 5 + cj] * LOG2E_F);
        const float E3 = ex2f_(trans[3 * 5 + cj] * LOG2E_F);
        const float E4 = ex2f_(trans[4 * 5 + cj] * LOG2E_F);

        float m = (act && ci == cj) ? 1.f : 0.f;
        int cexp = 0;
        const int t0 = 1 + 64 * wid;
        const int t1 = (t0 + 64 < S) ? (t0 + 64) : S;

        float fb[8];
#pragma unroll
        for (int u = 0; u < 8; u++) {
            int tq = t0 + u;
            fb[u] = (tq < t1) ? ex2f_(em[tq * EMS + cj] * LOG2E_F) : 1.f;
        }

        for (int tb = t0; tb < t1; tb += 8) {
            float fn[8];
#pragma unroll
            for (int u = 0; u < 8; u++) {
                int tq = tb + 8 + u;
                fn[u] = (tq < t1) ? ex2f_(em[tq * EMS + cj] * LOG2E_F) : 1.f;
            }
#pragma unroll
            for (int u = 0; u < 8; u++) {
                if (tb + u < t1) {
                    float a0 = __shfl_sync(0xffffffffu, m, b5 + 0);
                    float a1 = __shfl_sync(0xffffffffu, m, b5 + 1);
                    float a2 = __shfl_sync(0xffffffffu, m, b5 + 2);
                    float a3 = __shfl_sync(0xffffffffu, m, b5 + 3);
                    float a4 = __shfl_sync(0xffffffffu, m, b5 + 4);
                    float sm = (fmaf(a0, E0, a1 * E1) + fmaf(a2, E2, a3 * E3))
                               + a4 * E4;
                    m = act ? sm * fb[u] : 0.f;
                }
            }
            // renormalize by 2^-k, k = exponent of lane 0's entry (M_00)
            float m0 = __shfl_sync(0xffffffffu, m, 0);
            int kx = ((__float_as_int(m0) >> 23) & 255) - 127;
            m *= __int_as_float((127 - kx) << 23);
            cexp += kx;
#pragma unroll
            for (int u = 0; u < 8; u++) fb[u] = fn[u];
        }
        if (act) sM[wid * 25 + lane] = m;
        if (lane == 0) sC[wid] = cexp;
        asm volatile("bar.sync 1, 256;" ::: "memory");

        if (wid == 0) {
            const bool aj = lane < 5;
            float v = aj ? ex2f_((start_tr[lane] + em[lane]) * LOG2E_F) : 0.f;
            int ct = 0;
#pragma unroll
            for (int c = 0; c < 8; c++) {
                float a0 = __shfl_sync(0xffffffffu, v, 0);
                float a1 = __shfl_sync(0xffffffffu, v, 1);
                float a2 = __shfl_sync(0xffffffffu, v, 2);
                float a3 = __shfl_sync(0xffffffffu, v, 3);
                float a4 = __shfl_sync(0xffffffffu, v, 4);
                float nv = 0.f;
                if (aj) {
                    const float* Mc = sM + c * 25 + lane;
                    nv = fmaf(a0, Mc[0], fmaf(a1, Mc[5], fmaf(a2, Mc[10],
                         fmaf(a3, Mc[15], a4 * Mc[20]))));
                }
                float n0 = __shfl_sync(0xffffffffu, nv, 0);
                int kx = ((__float_as_int(n0) >> 23) & 255) - 127;
                v = nv * __int_as_float((127 - kx) << 23);
                ct += sC[c] + kx;
            }
            float r = aj ? v * ex2f_(end_tr[lane] * LOG2E_F) : 0.f;
            r += __shfl_xor_sync(0xffffffffu, r, 1);
            r += __shfl_xor_sync(0xffffffffu, r, 2);
            r += __shfl_xor_sync(0xffffffffu, r, 4);
            if (lane == 0)
                g_logz[b] = ((float)ct + lg2f_(fmaxf(r, 1e-38f))) * LN2_F;
        }
    }
}

// ---------------------------------------------------------------------------
// Kernel 3: loss = -sum_b(num_b - logz_b) / (B*S)
// ---------------------------------------------------------------------------
__global__ __launch_bounds__(64) void k_final(float* __restrict__ out) {
    const int t = threadIdx.x;
    float v = g_num[t] - g_logz[t];
#pragma unroll
    for (int d = 16; d > 0; d >>= 1)
        v += __shfl_xor_sync(0xffffffffu, v, d);
    __shared__ float sh[2];
    if ((t & 31) == 0) sh[t >> 5] = v;
    __syncthreads();
    if (t == 0) out[0] = -(sh[0] + sh[1]) * (1.0f / (float)(B * S));
}

// ---------------------------------------------------------------------------
// Launch. Inputs: feats f32, labels i32, mask bool (all ones, unused),
// W_tag f32, b_tag f32, start_trans f32, end_trans f32, trans f32, weights f32.
// Output: [loss, paths(B*S)] as float32.
// ---------------------------------------------------------------------------
extern "C" void kernel_launch(void* const* d_in, const int* in_sizes, int n_in,
                              void* d_out, int out_size) {
    (void)in_sizes; (void)n_in; (void)out_size;
    const float* feats  = (const float*)d_in[0];
    const int*   labels = (const int*)d_in[1];
    const float* W      = (const float*)d_in[3];
    const float* bias   = (const float*)d_in[4];
    const float* st     = (const float*)d_in[5];
    const float* en     = (const float*)d_in[6];
    const float* tr     = (const float*)d_in[7];
    const float* wt     = (const float*)d_in[8];
    float* out = (float*)d_out;

    k_emis<<<2048, 256>>>(feats, W, bias);
    k_crf<<<128, 288>>>(labels, st, en, tr, wt, out);
    k_final<<<1, 64>>>(out);
}

// round 16
// speedup vs baseline: 1.2223x; 1.0421x over previous
#include <cuda_runtime.h>
#include <math.h>

#define B 64
#define S 512
#define H 1024
#define L 5
#define EMS 8   // emission row stride (padded for aligned float4 loads)

#define LOG2E_F 1.4426950408889634f
#define LN2_F   0.6931471805599453f

// Scratch (static device globals). +16 pad: branch-free prefetch reads t=512.
__device__ float g_emis[B * S * EMS + 16];
__device__ float g_num[B];
__device__ float g_logz[B];

__device__ __forceinline__ float ex2f_(float x) {
    float r; asm("ex2.approx.ftz.f32 %0, %1;" : "=f"(r) : "f"(x)); return r;
}
__device__ __forceinline__ float lg2f_(float x) {
    float r; asm("lg2.approx.f32 %0, %1;" : "=f"(r) : "f"(x)); return r;
}

__device__ __forceinline__ void dot4(float& a, const float4& v, const float4& wv) {
    a = fmaf(v.x, wv.x, fmaf(v.y, wv.y, fmaf(v.z, wv.z, fmaf(v.w, wv.w, a))));
}

// ---------------------------------------------------------------------------
// Kernel 1: emissions = relu(feats @ W + b)   (R11 config: best measured)
// Warp owns 4 rows, lane owns float4 slice (lane + 32*i): contiguous 512B
// warp LDGs, prefetch distance 2 (8 LDG.128 in flight / warp).
// W transposed in smem (LDS.128, conflict-free). 1024 blocks x 256, 3 blk/SM.
// ---------------------------------------------------------------------------
__global__ __launch_bounds__(256, 3) void k_emis(const float* __restrict__ feats,
                                                 const float* __restrict__ Wg,
                                                 const float* __restrict__ bias) {
    __shared__ float sWT[5 * 1024];   // sWT[l*1024 + k] = W[k][l]
    const int t = threadIdx.x;
    for (int i = t; i < H * L; i += 256) {
        const int k = i / 5, l = i - 5 * k;
        sWT[l * 1024 + k] = Wg[i];
    }
    __syncthreads();

    const int lane = t & 31, w = t >> 5;
    const int row0 = blockIdx.x * 32 + w * 4;
    const float4* p0 = (const float4*)(feats + (size_t)(row0 + 0) * H);
    const float4* p1 = (const float4*)(feats + (size_t)(row0 + 1) * H);
    const float4* p2 = (const float4*)(feats + (size_t)(row0 + 2) * H);
    const float4* p3 = (const float4*)(feats + (size_t)(row0 + 3) * H);

    float acc[4][5];
#pragma unroll
    for (int r = 0; r < 4; r++)
#pragma unroll
        for (int l = 0; l < 5; l++) acc[r][l] = 0.f;

    float4 xa0 = p0[lane],      xa1 = p1[lane],      xa2 = p2[lane],      xa3 = p3[lane];
    float4 xb0 = p0[lane + 32], xb1 = p1[lane + 32], xb2 = p2[lane + 32], xb3 = p3[lane + 32];

#pragma unroll
    for (int i = 0; i < 8; i++) {
        float4 xc0, xc1, xc2, xc3;
        if (i < 6) {
            const int idx = lane + 32 * (i + 2);
            xc0 = p0[idx]; xc1 = p1[idx]; xc2 = p2[idx]; xc3 = p3[idx];
        }
        const int ko = (lane + 32 * i) * 4;
        const float4 w0 = *(const float4*)(sWT + 0 * 1024 + ko);
        const float4 w1 = *(const float4*)(sWT + 1 * 1024 + ko);
        const float4 w2 = *(const float4*)(sWT + 2 * 1024 + ko);
        const float4 w3 = *(const float4*)(sWT + 3 * 1024 + ko);
        const float4 w4 = *(const float4*)(sWT + 4 * 1024 + ko);

        dot4(acc[0][0], xa0, w0); dot4(acc[0][1], xa0, w1);
        dot4(acc[0][2], xa0, w2); dot4(acc[0][3], xa0, w3);
        dot4(acc[0][4], xa0, w4);
        dot4(acc[1][0], xa1, w0); dot4(acc[1][1], xa1, w1);
        dot4(acc[1][2], xa1, w2); dot4(acc[1][3], xa1, w3);
        dot4(acc[1][4], xa1, w4);
        dot4(acc[2][0], xa2, w0); dot4(acc[2][1], xa2, w1);
        dot4(acc[2][2], xa2, w2); dot4(acc[2][3], xa2, w3);
        dot4(acc[2][4], xa2, w4);
        dot4(acc[3][0], xa3, w0); dot4(acc[3][1], xa3, w1);
        dot4(acc[3][2], xa3, w2); dot4(acc[3][3], xa3, w3);
        dot4(acc[3][4], xa3, w4);

        xa0 = xb0; xa1 = xb1; xa2 = xb2; xa3 = xb3;
        if (i < 6) { xb0 = xc0; xb1 = xc1; xb2 = xc2; xb3 = xc3; }
    }

    // butterfly reduce all 20 accumulators over the 32 lanes
#pragma unroll
    for (int r = 0; r < 4; r++)
#pragma unroll
        for (int l = 0; l < 5; l++) {
#pragma unroll
            for (int d = 16; d > 0; d >>= 1)
                acc[r][l] += __shfl_xor_sync(0xffffffffu, acc[r][l], d);
        }

    float val = 0.f;
#pragma unroll
    for (int r = 0; r < 4; r++)
#pragma unroll
        for (int l = 0; l < 5; l++)
            if (lane == r * 5 + l) val = acc[r][l];
    if (lane < 20) {
        const int r = lane / 5, l = lane - 5 * (lane / 5);
        g_emis[(size_t)(row0 + r) * EMS + l] = fmaxf(val + bias[l], 0.f);
    }
}

// packed [5]->[5] map composition: returns f∘g (g applied first)
__device__ __forceinline__ int fcompose(int f, int g) {
    int r = 0;
#pragma unroll
    for (int x = 0; x < 5; x++) {
        int gx = (g >> (3 * x)) & 7;
        int fx = (f >> (3 * gx)) & 7;
        r |= fx << (3 * x);
    }
    return r;
}

// ---------------------------------------------------------------------------
// Kernel 2: CRF (R15, unchanged). Grid = 128 blocks x 288 threads:
//   blocks 0..63  : warp 8 = pass-A Viterbi (shfl-step, branch-free groups,
//       bit-exact), boundary store per 64-step super-group; warps 0..7 sleep
//       then pass-B backpointer chunks (branch-free); warp 8 backtrace.
//   blocks 64..127: warps 0..7 forward chunk matrices -> warp 0 combine
//       (logZ); warp 8 numerator.
// ---------------------------------------------------------------------------
__global__ __launch_bounds__(288) void k_crf(const int* __restrict__ labels,
                                             const float* __restrict__ start_tr,
                                             const float* __restrict__ end_tr,
                                             const float* __restrict__ trans,
                                             const float* __restrict__ wts,
                                             float* __restrict__ out) {
    const int bid = blockIdx.x;
    const int tid = threadIdx.x;
    const int wid = tid >> 5;
    const int lane = tid & 31;

    if (bid < 64) {
        // ==================== Viterbi block (batch = bid) ==================
        const int b = bid;
        const float* em = g_emis + (size_t)b * (S * EMS);
        __shared__ int   s_bp[S];
        __shared__ float sBnd[8 * 5];

        if (wid == 8) {
            // ===== pass A: shfl-step value-only Viterbi (branch-free) ======
            const int j = lane % 5;   // lanes 0..4 canonical, others mirror
            const float T0 = trans[0 * 5 + j];
            const float T1 = trans[1 * 5 + j];
            const float T2 = trans[2 * 5 + j];
            const float T3 = trans[3 * 5 + j];
            const float T4 = trans[4 * 5 + j];
            float v = start_tr[j] + em[j];
            if (lane < 5) sBnd[lane] = v;

            float ec[8], en[8];
#pragma unroll
            for (int u = 0; u < 8; u++) ec[u] = em[(1 + u) * EMS + j];

            int tt = 1;   // index of ec[0]
#define VSTEP(EV) { \
                float v0 = __shfl_sync(0xffffffffu, v, 0); \
                float v1 = __shfl_sync(0xffffffffu, v, 1); \
                float v2 = __shfl_sync(0xffffffffu, v, 2); \
                float v3 = __shfl_sync(0xffffffffu, v, 3); \
                float v4 = __shfl_sync(0xffffffffu, v, 4); \
                float c0 = v0 + T0, c1 = v1 + T1, c2 = v2 + T2; \
                float c3 = v3 + T3, c4 = v4 + T4; \
                float best = fmaxf(fmaxf(fmaxf(c0, c1), fmaxf(c2, c3)), c4); \
                v = best + (EV); }

#pragma unroll 1
            for (int sg = 0; sg < 7; sg++) {        // 7 x 64 steps (t 1..448)
#pragma unroll
                for (int grp = 0; grp < 8; grp++) {
#pragma unroll
                    for (int u = 0; u < 8; u++) en[u] = em[(tt + 8 + u) * EMS + j];
#pragma unroll
                    for (int u = 0; u < 8; u++) VSTEP(ec[u])
                    tt += 8;
#pragma unroll
                    for (int u = 0; u < 8; u++) ec[u] = en[u];
                }
                if (lane < 5) sBnd[(sg + 1) * 5 + lane] = v;
            }
            // epilogue: 56 steps (t 449..504) + 7 tail (505..511)
#pragma unroll 1
            for (int grp = 0; grp < 7; grp++) {
#pragma unroll
                for (int u = 0; u < 8; u++) en[u] = em[(tt + 8 + u) * EMS + j];
#pragma unroll
                for (int u = 0; u < 8; u++) VSTEP(ec[u])
                tt += 8;
#pragma unroll
                for (int u = 0; u < 8; u++) ec[u] = en[u];
            }
#pragma unroll
            for (int u = 0; u < 7; u++) VSTEP(ec[u])
#undef VSTEP

            // final tag: first-occurrence argmax over (v + end)
            float sc = v + end_tr[j];
            float s0 = __shfl_sync(0xffffffffu, sc, 0);
            float s1 = __shfl_sync(0xffffffffu, sc, 1);
            float s2 = __shfl_sync(0xffffffffu, sc, 2);
            float s3 = __shfl_sync(0xffffffffu, sc, 3);
            float s4 = __shfl_sync(0xffffffffu, sc, 4);
            float bb = fmaxf(fmaxf(fmaxf(s0, s1), fmaxf(s2, s3)), s4);
            int last = (s0 == bb) ? 0 : (s1 == bb) ? 1
                     : (s2 == bb) ? 2 : (s3 == bb) ? 3 : 4;

            __syncthreads();   // boundaries ready -> wake warps 0..7
            __syncthreads();   // s_bp complete

            // ---- backtrace via suffix scan of packed [5]->[5] maps --------
            const int IDMAP = 0 | (1 << 3) | (2 << 6) | (3 << 9) | (4 << 12);
            int wv[16];
            const int tb2 = lane * 16;
#pragma unroll
            for (int u = 0; u < 16; u++) wv[u] = s_bp[tb2 + u];
            if (lane == 0) wv[0] = IDMAP;

            int G = wv[0];
#pragma unroll
            for (int u = 1; u < 16; u++) G = fcompose(G, wv[u]);

            int Tm = G;
#pragma unroll
            for (int d = 1; d < 32; d <<= 1) {
                int o = __shfl_down_sync(0xffffffffu, Tm, d);
                Tm = (lane + d < 32) ? fcompose(Tm, o) : Tm;
            }
            int E = __shfl_down_sync(0xffffffffu, Tm, 1);
            if (lane == 31) E = IDMAP;

            int tag = (E >> (3 * last)) & 7;
            float* po = out + 1 + (size_t)b * S;
            po[tb2 + 15] = (float)tag;
#pragma unroll
            for (int u = 15; u >= 1; u--) {
                tag = (wv[u] >> (3 * tag)) & 7;
                po[tb2 + u - 1] = (float)tag;
            }
        } else {
            __syncthreads();   // sleep until pass-A boundaries ready

            // ---- pass B: shfl-step Viterbi chunk with backpointers --------
            const int j = lane % 5;
            const float T0 = trans[0 * 5 + j];
            const float T1 = trans[1 * 5 + j];
            const float T2 = trans[2 * 5 + j];
            const float T3 = trans[3 * 5 + j];
            const float T4 = trans[4 * 5 + j];
            float v = sBnd[wid * 5 + j];
            int tt = 1 + 64 * wid;
            const int nfull = (wid < 7) ? 8 : 7;   // groups of 8 steps

            float ec[8], en[8];
#pragma unroll
            for (int u = 0; u < 8; u++) ec[u] = em[(tt + u) * EMS + j];

#define VSTEPB(EV, TC) { \
                float v0 = __shfl_sync(0xffffffffu, v, 0); \
                float v1 = __shfl_sync(0xffffffffu, v, 1); \
                float v2 = __shfl_sync(0xffffffffu, v, 2); \
                float v3 = __shfl_sync(0xffffffffu, v, 3); \
                float v4 = __shfl_sync(0xffffffffu, v, 4); \
                float c0 = v0 + T0, c1 = v1 + T1, c2 = v2 + T2; \
                float c3 = v3 + T3, c4 = v4 + T4; \
                float best = fmaxf(fmaxf(fmaxf(c0, c1), fmaxf(c2, c3)), c4); \
                int bp = (c0 == best) ? 0 : (c1 == best) ? 1 \
                       : (c2 == best) ? 2 : (c3 == best) ? 3 : 4; \
                v = best + (EV); \
                unsigned pk = __reduce_add_sync(0xffffffffu, \
                              (lane < 5) ? ((unsigned)bp << (3 * j)) : 0u); \
                if (lane == 0) s_bp[(TC)] = (int)pk; }

#pragma unroll 1
            for (int grp = 0; grp < nfull; grp++) {
#pragma unroll
                for (int u = 0; u < 8; u++) en[u] = em[(tt + 8 + u) * EMS + j];
#pragma unroll
                for (int u = 0; u < 8; u++) VSTEPB(ec[u], tt + u)
                tt += 8;
#pragma unroll
                for (int u = 0; u < 8; u++) ec[u] = en[u];
            }
            if (wid == 7) {
#pragma unroll
                for (int u = 0; u < 7; u++) VSTEPB(ec[u], tt + u)
            }
#undef VSTEPB
            __syncthreads();   // s_bp complete
        }
        return;
    }

    // ===================== forward + numerator block =======================
    const int b = bid - 64;
    const float* em = g_emis + (size_t)b * (S * EMS);
    __shared__ float sM[8 * 25];
    __shared__ int   sC[8];

    if (wid == 8) {
        // ========================== numerator ==============================
        const int* lb = labels + b * S;
        float acc = 0.f;
#pragma unroll
        for (int it = 0; it < S / 32; it++) {
            const int s2 = lane + it * 32;
            int l0 = lb[s2];
            float term = wts[l0] * em[s2 * EMS + l0];
            if (s2 + 1 < S) {
                int l1 = lb[s2 + 1];
                term += trans[l0 * 5 + l1];
            }
            acc += term;
        }
#pragma unroll
        for (int d = 16; d > 0; d >>= 1)
            acc += __shfl_xor_sync(0xffffffffu, acc, d);
        if (lane == 0)
            g_num[b] = acc + start_tr[lb[0]] + end_tr[lb[S - 1]];
        return;
    }

    {
        // ---- forward: chunk transfer matrix (scaled prob) -----------------
        const int cj = lane % 5;        // column j
        const int ci = lane / 5;        // row i (>=5 for lanes 25..31)
        const bool act = lane < 25;
        const int b5 = lane - cj;       // 5*i
        const float E0 = ex2f_(trans[0 * 5 + cj] * LOG2E_F);
        const float E1 = ex2f_(trans[1 * 5 + cj] * LOG2E_F);
        const float E2 = ex2f_(trans[2 * 5 + cj] * LOG2E_F);
        const float E3 = ex2f_(trans[3 * 5 + cj] * LOG2E_F);
        const float E4 = ex2f_(trans[4 * 5 + cj] * LOG2E_F);

        float m = (act && ci == cj) ? 1.f : 0.f;
        int cexp = 0;
        const int t0 = 1 + 64 * wid;
        const int t1 = (t0 + 64 < S) ? (t0 + 64) : S;

        float fb[8];
#pragma unroll
        for (int u = 0; u < 8; u++) {
            int tq = t0 + u;
            fb[u] = (tq < t1) ? ex2f_(em[tq * EMS + cj] * LOG2E_F) : 1.f;
        }

        for (int tb = t0; tb < t1; tb += 8) {
            float fn[8];
#pragma unroll
            for (int u = 0; u < 8; u++) {
                int tq = tb + 8 + u;
                fn[u] = (tq < t1) ? ex2f_(em[tq * EMS + cj] * LOG2E_F) : 1.f;
            }
#pragma unroll
            for (int u = 0; u < 8; u++) {
                if (tb + u < t1) {
                    float a0 = __shfl_sync(0xffffffffu, m, b5 + 0);
                    float a1 = __shfl_sync(0xffffffffu, m, b5 + 1);
                    float a2 = __shfl_sync(0xffffffffu, m, b5 + 2);
                    float a3 = __shfl_sync(0xffffffffu, m, b5 + 3);
                    float a4 = __shfl_sync(0xffffffffu, m, b5 + 4);
                    float sm = (fmaf(a0, E0, a1 * E1) + fmaf(a2, E2, a3 * E3))
                               + a4 * E4;
                    m = act ? sm * fb[u] : 0.f;
                }
            }
            // renormalize by 2^-k, k = exponent of lane 0's entry (M_00)
            float m0 = __shfl_sync(0xffffffffu, m, 0);
            int kx = ((__float_as_int(m0) >> 23) & 255) - 127;
            m *= __int_as_float((127 - kx) << 23);
            cexp += kx;
#pragma unroll
            for (int u = 0; u < 8; u++) fb[u] = fn[u];
        }
        if (act) sM[wid * 25 + lane] = m;
        if (lane == 0) sC[wid] = cexp;
        asm volatile("bar.sync 1, 256;" ::: "memory");

        if (wid == 0) {
            const bool aj = lane < 5;
            float v = aj ? ex2f_((start_tr[lane] + em[lane]) * LOG2E_F) : 0.f;
            int ct = 0;
#pragma unroll
            for (int c = 0; c < 8; c++) {
                float a0 = __shfl_sync(0xffffffffu, v, 0);
                float a1 = __shfl_sync(0xffffffffu, v, 1);
                float a2 = __shfl_sync(0xffffffffu, v, 2);
                float a3 = __shfl_sync(0xffffffffu, v, 3);
                float a4 = __shfl_sync(0xffffffffu, v, 4);
                float nv = 0.f;
                if (aj) {
                    const float* Mc = sM + c * 25 + lane;
                    nv = fmaf(a0, Mc[0], fmaf(a1, Mc[5], fmaf(a2, Mc[10],
                         fmaf(a3, Mc[15], a4 * Mc[20]))));
                }
                float n0 = __shfl_sync(0xffffffffu, nv, 0);
                int kx = ((__float_as_int(n0) >> 23) & 255) - 127;
                v = nv * __int_as_float((127 - kx) << 23);
                ct += sC[c] + kx;
            }
            float r = aj ? v * ex2f_(end_tr[lane] * LOG2E_F) : 0.f;
            r += __shfl_xor_sync(0xffffffffu, r, 1);
            r += __shfl_xor_sync(0xffffffffu, r, 2);
            r += __shfl_xor_sync(0xffffffffu, r, 4);
            if (lane == 0)
                g_logz[b] = ((float)ct + lg2f_(fmaxf(r, 1e-38f))) * LN2_F;
        }
    }
}

// ---------------------------------------------------------------------------
// Kernel 3: loss = -sum_b(num_b - logz_b) / (B*S)
// ---------------------------------------------------------------------------
__global__ __launch_bounds__(64) void k_final(float* __restrict__ out) {
    const int t = threadIdx.x;
    float v = g_num[t] - g_logz[t];
#pragma unroll
    for (int d = 16; d > 0; d >>= 1)
        v += __shfl_xor_sync(0xffffffffu, v, d);
    __shared__ float sh[2];
    if ((t & 31) == 0) sh[t >> 5] = v;
    __syncthreads();
    if (t == 0) out[0] = -(sh[0] + sh[1]) * (1.0f / (float)(B * S));
}

// ---------------------------------------------------------------------------
// Launch. Inputs: feats f32, labels i32, mask bool (all ones, unused),
// W_tag f32, b_tag f32, start_trans f32, end_trans f32, trans f32, weights f32.
// Output: [loss, paths(B*S)] as float32.
// ---------------------------------------------------------------------------
extern "C" void kernel_launch(void* const* d_in, const int* in_sizes, int n_in,
                              void* d_out, int out_size) {
    (void)in_sizes; (void)n_in; (void)out_size;
    const float* feats  = (const float*)d_in[0];
    const int*   labels = (const int*)d_in[1];
    const float* W      = (const float*)d_in[3];
    const float* bias   = (const float*)d_in[4];
    const float* st     = (const float*)d_in[5];
    const float* en     = (const float*)d_in[6];
    const float* tr     = (const float*)d_in[7];
    const float* wt     = (const float*)d_in[8];
    float* out = (float*)d_out;

    k_emis<<<1024, 256>>>(feats, W, bias);
    k_crf<<<128, 288>>>(labels, st, en, tr, wt, out);
    k_final<<<1, 64>>>(out);
}